// round 17
// baseline (speedup 1.0000x reference)
#include <cuda_runtime.h>
#include <cuda_fp16.h>
#include <mma.h>
#include <cstdint>
#include <cstddef>

using namespace nvcuda;

// ---------------- problem constants ----------------
#define N0C 120000
#define N1C 30000
#define N2C 6000
#define E0C 480000
#define E1C 96000
#define DC  128
#define RC  8
#define NBC 4
#define KNODE (DC + RC*DC)   // 1152
#define CAP  64
#define OVF_MAX 8192

// ---------------- device scratch ----------------
__device__ __half g_h0h[(size_t)N0C * DC];
__device__ __half g_acc0h[(size_t)N1C * RC * DC];
__device__ __half g_h1h[(size_t)N1C * DC];
__device__ __half g_acc1h[(size_t)N2C * RC * DC];
__device__ __half g_h2h[(size_t)N2C * DC];

__device__ int g_cnt0[N1C];            // static zero-init; reset by gemm_node each launch
__device__ int g_cnt1[N2C];
__device__ unsigned int g_pay0[(size_t)N1C * CAP];
__device__ unsigned int g_pay1[(size_t)N2C * CAP];
__device__ int g_ovfn0[1];
__device__ int g_ovfn1[1];
__device__ uint2 g_ovf0[OVF_MAX];
__device__ uint2 g_ovf1[OVF_MAX];

__device__ __half g_WPre_hi[DC * DC];
__device__ __half g_WPre_lo[DC * DC];
__device__ __half g_W0_hi[KNODE * DC];
__device__ __half g_W0_lo[KNODE * DC];
__device__ __half g_W1_hi[KNODE * DC];
__device__ __half g_W1_lo[KNODE * DC];
__device__ __half g_WPost_hi[DC * DC];
__device__ __half g_WPost_lo[DC * DC];

// ---------------- helpers ----------------
__device__ __forceinline__ uint32_t smem_u32(const void* p) {
    uint32_t a;
    asm("{ .reg .u64 t; cvta.to.shared.u64 t, %1; cvt.u32.u64 %0, t; }" : "=r"(a) : "l"(p));
    return a;
}
__device__ __forceinline__ void cp16(uint32_t dst, const void* src, int sz) {
    asm volatile("cp.async.cg.shared.global [%0], [%1], 16, %2;"
                 :: "r"(dst), "l"(src), "r"(sz) : "memory");
}
__device__ __forceinline__ void cp_commit() {
    asm volatile("cp.async.commit_group;" ::: "memory");
}
template <int N>
__device__ __forceinline__ void cp_wait() {
    asm volatile("cp.async.wait_group %0;" :: "n"(N) : "memory");
}

// ---------------- fused setup (weight folds) + bucketing ----------------
#define SB_PRE  64
#define SB_POST 64
#define SB_NODE 576
#define SB_W    (SB_PRE + SB_POST + 2*SB_NODE)   // 1280
#define NBK0 ((E0C + 255) / 256)
#define NBK1 ((E1C + 255) / 256)
#define SB_TOTAL (SB_W + NBK0 + NBK1)

__device__ __forceinline__ void split_store(float v, __half* hi, __half* lo, int idx) {
    __half h = __float2half(v);
    hi[idx] = h;
    lo[idx] = __float2half(v - __half2float(h));
}

__device__ void build_node_W(int idx, const float* root, const float* basis,
                             const float* comp, __half* hi, __half* lo) {
    int k = idx >> 7, n = idx & 127;
    float v;
    if (k < DC) {
        v = root[k * DC + n];
    } else {
        int r = (k - DC) >> 7;
        int i = (k - DC) & 127;
        v = 0.f;
        #pragma unroll
        for (int b = 0; b < NBC; b++)
            v += comp[r * NBC + b] * basis[((size_t)b * DC + i) * DC + n];
    }
    split_store(v, hi, lo, idx);
}

__global__ void setup_bucket(const float* __restrict__ preW, const float* __restrict__ postW,
                             const float* __restrict__ root0, const float* __restrict__ basis0,
                             const float* __restrict__ comp0,
                             const float* __restrict__ root1, const float* __restrict__ basis1,
                             const float* __restrict__ comp1,
                             __half* preh, __half* prel, __half* posth, __half* postl,
                             __half* w0h, __half* w0l, __half* w1h, __half* w1l,
                             const int* __restrict__ src0, const int* __restrict__ dst0,
                             const int* __restrict__ eid0,
                             const int* __restrict__ src1, const int* __restrict__ dst1,
                             const int* __restrict__ eid1,
                             const int* __restrict__ et_all,
                             int* __restrict__ cnt0, unsigned int* __restrict__ pay0,
                             int* __restrict__ ovfn0, uint2* __restrict__ ovf0,
                             int* __restrict__ cnt1, unsigned int* __restrict__ pay1,
                             int* __restrict__ ovfn1, uint2* __restrict__ ovf1) {
    int b = blockIdx.x;
    int t = threadIdx.x;
    if (b < SB_PRE) {
        int idx = b * 256 + t;
        split_store(preW[idx], preh, prel, idx);
    } else if (b < SB_PRE + SB_POST) {
        int idx = (b - SB_PRE) * 256 + t;
        split_store(postW[idx], posth, postl, idx);
    } else if (b < SB_PRE + SB_POST + SB_NODE) {
        int idx = (b - SB_PRE - SB_POST) * 256 + t;
        build_node_W(idx, root0, basis0, comp0, w0h, w0l);
    } else if (b < SB_W) {
        int idx = (b - SB_PRE - SB_POST - SB_NODE) * 256 + t;
        build_node_W(idx, root1, basis1, comp1, w1h, w1l);
    } else {
        int bb = b - SB_W;
        const int* src; const int* dst; const int* eid;
        int* cnt; unsigned int* pay; int* ovfn; uint2* ovf;
        int e, E;
        if (bb < NBK0) {
            e = bb * 256 + t; E = E0C;
            src = src0; dst = dst0; eid = eid0;
            cnt = cnt0; pay = pay0; ovfn = ovfn0; ovf = ovf0;
        } else {
            e = (bb - NBK0) * 256 + t; E = E1C;
            src = src1; dst = dst1; eid = eid1;
            cnt = cnt1; pay = pay1; ovfn = ovfn1; ovf = ovf1;
        }
        if (e >= E) return;
        int d = dst[e];
        unsigned int p = (unsigned int)src[e] | ((unsigned int)et_all[eid[e]] << 24);
        int i = atomicAdd(&cnt[d], 1);
        if (i < CAP) {
            pay[(size_t)d * CAP + i] = p;
        } else {
            int o = atomicAdd(ovfn, 1);
            if (o < OVF_MAX) ovf[o] = make_uint2(p, (unsigned int)d);
        }
    }
}

// ---------------- gather-aggregate: 2 warps per dst, lane-private smem accumulators ----------------
__global__ __launch_bounds__(256)
void gather_kernel(const int* __restrict__ cnt, const unsigned int* __restrict__ pay,
                   const __half* __restrict__ h, __half* __restrict__ acc, int N) {
    __shared__ float s_acc[8][RC * 64];
    int d = blockIdx.x * 4 + (threadIdx.x >> 6);
    int wid = threadIdx.x >> 5;
    int half = wid & 1;
    int lane = threadIdx.x & 31;
    if (d >= N) return;
    int ntot = cnt[d];
    int n = min(ntot, CAP);

    const unsigned int* pl = pay + (size_t)d * CAP;
    unsigned int myp[2];
    #pragma unroll
    for (int q = 0; q < 2; q++)
        myp[q] = (q * 32 + lane < n) ? __ldg(pl + q * 32 + lane) : 0u;

    const int featOff = half * 64 + lane * 2;
    float* aw = s_acc[wid];

    #pragma unroll
    for (int r = 0; r < RC; r++)
        *reinterpret_cast<float2*>(aw + r * 64 + lane * 2) = make_float2(0.f, 0.f);

    #define ACC_EDGE(P)                                                         \
        do {                                                                    \
            unsigned int _p = (P);                                              \
            uint32_t _u = *reinterpret_cast<const uint32_t*>(                   \
                h + (size_t)(_p & 0xFFFFFFu) * DC + featOff);                   \
            float2 _f = __half22float2(*(__half2*)&_u);                         \
            int _et = (int)(_p >> 24);                                          \
            float2* _ap = reinterpret_cast<float2*>(aw + _et * 64 + lane * 2);  \
            float2 _c = *_ap;                                                   \
            _c.x += _f.x; _c.y += _f.y;                                         \
            *_ap = _c;                                                          \
        } while (0)

    int j = 0;
    for (; j + 4 <= n; j += 4) {
        unsigned int p0 = __shfl_sync(0xffffffffu, myp[(j + 0) >> 5], (j + 0) & 31);
        unsigned int p1 = __shfl_sync(0xffffffffu, myp[(j + 1) >> 5], (j + 1) & 31);
        unsigned int p2 = __shfl_sync(0xffffffffu, myp[(j + 2) >> 5], (j + 2) & 31);
        unsigned int p3 = __shfl_sync(0xffffffffu, myp[(j + 3) >> 5], (j + 3) & 31);
        ACC_EDGE(p0);
        ACC_EDGE(p1);
        ACC_EDGE(p2);
        ACC_EDGE(p3);
    }
    for (; j < n; j++) {
        unsigned int p = __shfl_sync(0xffffffffu, myp[j >> 5], j & 31);
        ACC_EDGE(p);
    }
    #undef ACC_EDGE

    float inv = 1.0f / fmaxf((float)ntot, 1.0f);
    __half* out = acc + (size_t)d * (RC * DC) + featOff;
    #pragma unroll
    for (int r = 0; r < RC; r++) {
        float2 c = *reinterpret_cast<float2*>(aw + r * 64 + lane * 2);
        __half2 o = __floats2half2_rn(c.x * inv, c.y * inv);
        *reinterpret_cast<__half2*>(out + r * DC) = o;
    }
}

// ================= GEMM kernels =================
enum { MODE_PRE = 0, MODE_NODE = 1, MODE_POST = 2 };
#define LDCS 132

// ---- epilogue for 256-thread kernels (2 threads/row); LN for NODE via shfl ----
template <int MODE>
__device__ __forceinline__ void epilogue(char* smem, int offC, const float* s_bias,
                                         const float* s_g, const float* s_be,
                                         __half* outH, float* outF, int mBase, int M, int t) {
    const float* Cs = (const float*)(smem + offC);
    int row = t >> 1;
    int half = t & 1;
    int grow = mBase + row;
    const float* crow = Cs + row * LDCS + half * 64;
    float v[64];
    #pragma unroll
    for (int q = 0; q < 16; q++) {
        float4 cv = *reinterpret_cast<const float4*>(crow + q * 4);
        v[q * 4 + 0] = cv.x + s_bias[half * 64 + q * 4 + 0];
        v[q * 4 + 1] = cv.y + s_bias[half * 64 + q * 4 + 1];
        v[q * 4 + 2] = cv.z + s_bias[half * 64 + q * 4 + 2];
        v[q * 4 + 3] = cv.w + s_bias[half * 64 + q * 4 + 3];
    }
    if (MODE == MODE_NODE) {
        float s1 = 0.f, s2 = 0.f;
        #pragma unroll
        for (int j = 0; j < 64; j++) { s1 += v[j]; s2 += v[j] * v[j]; }
        s1 += __shfl_xor_sync(0xffffffffu, s1, 1);
        s2 += __shfl_xor_sync(0xffffffffu, s2, 1);
        float mu = s1 * (1.f / 128.f);
        float var = s2 * (1.f / 128.f) - mu * mu;
        float rs = rsqrtf(var + 1e-5f);
        #pragma unroll
        for (int j = 0; j < 64; j++)
            v[j] = fmaxf((v[j] - mu) * rs * s_g[half * 64 + j] + s_be[half * 64 + j], 0.f);
    } else if (MODE == MODE_PRE) {
        #pragma unroll
        for (int j = 0; j < 64; j++) v[j] = fmaxf(v[j], 0.f);
    }
    if (grow < M) {
        if (MODE == MODE_POST) {
            #pragma unroll
            for (int q = 0; q < 16; q++) {
                float4 o = make_float4(v[q * 4], v[q * 4 + 1], v[q * 4 + 2], v[q * 4 + 3]);
                *reinterpret_cast<float4*>(outF + (size_t)grow * DC + half * 64 + q * 4) = o;
            }
        } else {
            #pragma unroll
            for (int q = 0; q < 8; q++) {
                __half2 h0 = __floats2half2_rn(v[q * 8 + 0], v[q * 8 + 1]);
                __half2 h1 = __floats2half2_rn(v[q * 8 + 2], v[q * 8 + 3]);
                __half2 h2 = __floats2half2_rn(v[q * 8 + 4], v[q * 8 + 5]);
                __half2 h3 = __floats2half2_rn(v[q * 8 + 6], v[q * 8 + 7]);
                uint4 o;
                o.x = *(uint32_t*)&h0; o.y = *(uint32_t*)&h1;
                o.z = *(uint32_t*)&h2; o.w = *(uint32_t*)&h3;
                *reinterpret_cast<uint4*>(outH + (size_t)grow * DC + half * 64 + q * 8) = o;
            }
        }
    }
}

// ---- K=128 single-stage GEMM; USE_LO selects split-B (post) vs single-B (pre) ----
#define LDK 136
#define K1_OFF_BIAS 0
#define K1_OFF_A    2048
#define K1_OFF_BH   (K1_OFF_A + 128*LDK*2)
#define K1_OFF_BL   (K1_OFF_BH + 128*LDK*2)
#define K1_SMEM     (K1_OFF_BL + 128*LDK*2)     // 106496
#define K1_SMEM_NL  (K1_OFF_BL)                 // 71680
#define K1_OFF_C    K1_OFF_A

template <int MODE, bool USE_LO>
__global__ __launch_bounds__(256, 2)
void gemm_k128(const float* __restrict__ A32,
               const __half* __restrict__ A16,
               const __half* __restrict__ Whi,
               const __half* __restrict__ Wlo,
               const float* __restrict__ bias,
               __half* __restrict__ outH,
               float* __restrict__ outF,
               int M) {
    extern __shared__ char smem[];
    const uint32_t sb = smem_u32(smem);
    const int t = threadIdx.x;
    const int w = t >> 5;
    const int wm = w >> 1;
    const int wn = w & 1;
    const int mBase = blockIdx.x * 128;

    float* s_bias = (float*)(smem + K1_OFF_BIAS);
    if (t < 128) s_bias[t] = bias[t];

    __half* As = (__half*)(smem + K1_OFF_A);
    __half* Bh = (__half*)(smem + K1_OFF_BH);
    __half* Bl = (__half*)(smem + K1_OFF_BL);

    #pragma unroll
    for (int it = 0; it < 8; it++) {
        int v = it * 256 + t;
        int row = v >> 4, seg = v & 15;
        uint32_t off = row * (LDK * 2) + seg * 16;
        cp16(sb + K1_OFF_BH + off, Whi + (size_t)row * DC + seg * 8, 16);
        if (USE_LO)
            cp16(sb + K1_OFF_BL + off, Wlo + (size_t)row * DC + seg * 8, 16);
    }
    cp_commit();

    if (MODE == MODE_PRE) {
        #pragma unroll
        for (int it = 0; it < 16; it++) {
            int v = it * 256 + t;
            int row = v >> 5, seg = v & 31;
            int g = mBase + row;
            float4 av = make_float4(0.f, 0.f, 0.f, 0.f);
            if (g < M) av = *reinterpret_cast<const float4*>(A32 + (size_t)g * DC + seg * 4);
            __half2 p0 = __floats2half2_rn(av.x, av.y);
            __half2 p1 = __floats2half2_rn(av.z, av.w);
            uint2 o;
            o.x = *(uint32_t*)&p0; o.y = *(uint32_t*)&p1;
            *reinterpret_cast<uint2*>(As + row * LDK + seg * 4) = o;
        }
    } else {
        #pragma unroll
        for (int it = 0; it < 8; it++) {
            int v = it * 256 + t;
            int row = v >> 4, seg = v & 15;
            int g = mBase + row;
            bool ok = g < M;
            cp16(sb + K1_OFF_A + row * (LDK * 2) + seg * 16,
                 A16 + (size_t)(ok ? g : 0) * DC + seg * 8, ok ? 16 : 0);
        }
        cp_commit();
    }
    cp_wait<0>();
    __syncthreads();

    wmma::fragment<wmma::accumulator, 16, 16, 16, float> acc[2][4];
    #pragma unroll
    for (int i = 0; i < 2; i++)
        #pragma unroll
        for (int j = 0; j < 4; j++)
            wmma::fill_fragment(acc[i][j], 0.f);

    #pragma unroll
    for (int ks = 0; ks < 8; ks++) {
        wmma::fragment<wmma::matrix_a, 16, 16, 16, __half, wmma::row_major> a[2];
        #pragma unroll
        for (int i = 0; i < 2; i++)
            wmma::load_matrix_sync(a[i], As + (wm * 32 + i * 16) * LDK + ks * 16, LDK);
        #pragma unroll
        for (int j = 0; j < 4; j++) {
            wmma::fragment<wmma::matrix_b, 16, 16, 16, __half, wmma::row_major> bh;
            wmma::load_matrix_sync(bh, Bh + (ks * 16) * LDK + wn * 64 + j * 16, LDK);
            #pragma unroll
            for (int i = 0; i < 2; i++)
                wmma::mma_sync(acc[i][j], a[i], bh, acc[i][j]);
            if (USE_LO) {
                wmma::fragment<wmma::matrix_b, 16, 16, 16, __half, wmma::row_major> bl;
                wmma::load_matrix_sync(bl, Bl + (ks * 16) * LDK + wn * 64 + j * 16, LDK);
                #pragma unroll
                for (int i = 0; i < 2; i++)
                    wmma::mma_sync(acc[i][j], a[i], bl, acc[i][j]);
            }
        }
    }

    __syncthreads();
    float* Cs = (float*)(smem + K1_OFF_C);
    #pragma unroll
    for (int i = 0; i < 2; i++)
        #pragma unroll
        for (int j = 0; j < 4; j++)
            wmma::store_matrix_sync(Cs + (wm * 32 + i * 16) * LDCS + wn * 64 + j * 16,
                                    acc[i][j], LDCS, wmma::mem_row_major);
    __syncthreads();
    epilogue<MODE>(smem, K1_OFF_C, s_bias, nullptr, nullptr, outH, outF, mBase, M, t);
}

// ---- K=1152 node GEMM: 256 threads, 8 warps (32x64 tiles), 3-stage cp.async ----
#define LDA 72
#define LDB 136
#define A_BUF 18432
#define B_BUF 17408
#define OFF_BIAS 0
#define OFF_G    512
#define OFF_BE   1024
#define OFF_A    2048
#define OFF_B    (OFF_A + 3*A_BUF)          // 57344
#define SMEM_TOT (OFF_B + 3*B_BUF)          // 109568
#define OFF_C    OFF_A

__global__ __launch_bounds__(256, 2)
void gemm_node(const __half* __restrict__ A,
               const __half* __restrict__ ACC,
               const __half* __restrict__ Whi,
               const float* __restrict__ bias,
               const float* __restrict__ gamma,
               const float* __restrict__ beta,
               __half* __restrict__ outH,
               int* __restrict__ cntReset,
               int M) {
    extern __shared__ char smem[];
    const uint32_t sb = smem_u32(smem);
    const int t = threadIdx.x;
    const int w = t >> 5;
    const int wm = w >> 1;       // 0..3 : 32-row group
    const int wn = w & 1;        // 0..1 : 64-col group
    const int mBase = blockIdx.x * 128;
    const int K = KNODE;

    // reset this block's slice of the bucket counters (gather already consumed them)
    if (t < 128 && mBase + t < M) cntReset[mBase + t] = 0;

    float* s_bias = (float*)(smem + OFF_BIAS);
    float* s_g    = (float*)(smem + OFF_G);
    float* s_be   = (float*)(smem + OFF_BE);
    if (t < 128) { s_bias[t] = bias[t]; s_g[t] = gamma[t]; s_be[t] = beta[t]; }

    wmma::fragment<wmma::accumulator, 16, 16, 16, float> acc[2][4];
    #pragma unroll
    for (int i = 0; i < 2; i++)
        #pragma unroll
        for (int j = 0; j < 4; j++)
            wmma::fill_fragment(acc[i][j], 0.f);

    const int nCh = K >> 6;   // 18

    auto issue = [&](int c) {
        int buf = c % 3;
        int k0 = c * 64;
        // A: 128 rows x 64 cols = 1024 cp16, 4 per thread
        #pragma unroll
        for (int it = 0; it < 4; it++) {
            int v = it * 256 + t;
            int row = v >> 3, seg = v & 7;
            int g = mBase + row;
            bool ok = g < M;
            const __half* src;
            if (k0 >= DC)
                src = ACC + (size_t)(ok ? g : 0) * (RC * DC) + (k0 - DC) + seg * 8;
            else
                src = A + (size_t)(ok ? g : 0) * DC + k0 + seg * 8;
            cp16(sb + OFF_A + buf * A_BUF + row * (LDA * 2) + seg * 16, src, ok ? 16 : 0);
        }
        // B: 64 rows x 128 cols = 1024 cp16, 4 per thread
        #pragma unroll
        for (int it = 0; it < 4; it++) {
            int v = it * 256 + t;
            int row = v >> 4, seg = v & 15;
            uint32_t d0 = sb + OFF_B + buf * B_BUF + row * (LDB * 2) + seg * 16;
            cp16(d0, Whi + (size_t)(k0 + row) * DC + seg * 8, 16);
        }
    };

    issue(0);
    cp_commit();
    issue(1);
    cp_commit();

    for (int c = 0; c < nCh; c++) {
        if (c + 2 < nCh) {
            issue(c + 2);
            cp_commit();
            cp_wait<2>();
        } else if (c + 1 < nCh) {
            cp_wait<1>();
        } else {
            cp_wait<0>();
        }
        __syncthreads();

        int buf = c % 3;
        const __half* As = (const __half*)(smem + OFF_A + buf * A_BUF);
        const __half* Bh = (const __half*)(smem + OFF_B + buf * B_BUF);

        #pragma unroll
        for (int ks = 0; ks < 4; ks++) {
            wmma::fragment<wmma::matrix_a, 16, 16, 16, __half, wmma::row_major> a[2];
            #pragma unroll
            for (int i = 0; i < 2; i++)
                wmma::load_matrix_sync(a[i], As + (wm * 32 + i * 16) * LDA + ks * 16, LDA);
            #pragma unroll
            for (int j = 0; j < 4; j++) {
                wmma::fragment<wmma::matrix_b, 16, 16, 16, __half, wmma::row_major> bh;
                wmma::load_matrix_sync(bh, Bh + (ks * 16) * LDB + wn * 64 + j * 16, LDB);
                #pragma unroll
                for (int i = 0; i < 2; i++)
                    wmma::mma_sync(acc[i][j], a[i], bh, acc[i][j]);
            }
        }
        __syncthreads();
    }

    float* Cs = (float*)(smem + OFF_C);
    #pragma unroll
    for (int i = 0; i < 2; i++)
        #pragma unroll
        for (int j = 0; j < 4; j++)
            wmma::store_matrix_sync(Cs + (wm * 32 + i * 16) * LDCS + wn * 64 + j * 16,
                                    acc[i][j], LDCS, wmma::mem_row_major);
    __syncthreads();
    epilogue<MODE_NODE>(smem, OFF_C, s_bias, s_g, s_be, outH, nullptr, mBase, M, t);
}

// ---------------- launch ----------------
extern "C" void kernel_launch(void* const* d_in, const int* in_sizes, int n_in,
                              void* d_out, int out_size) {
    const float* x     = (const float*)d_in[0];
    const int*   src0  = (const int*)d_in[1];
    const int*   dst0  = (const int*)d_in[2];
    const int*   eid0  = (const int*)d_in[3];
    const int*   src1  = (const int*)d_in[4];
    const int*   dst1  = (const int*)d_in[5];
    const int*   eid1  = (const int*)d_in[6];
    const int*   etall = (const int*)d_in[7];
    const float* preW  = (const float*)d_in[8];
    const float* preB  = (const float*)d_in[9];
    const float* basis0= (const float*)d_in[10];
    const float* comp0 = (const float*)d_in[11];
    const float* root0 = (const float*)d_in[12];
    const float* bias0 = (const float*)d_in[13];
    const float* g0    = (const float*)d_in[14];
    const float* be0   = (const float*)d_in[15];
    const float* basis1= (const float*)d_in[16];
    const float* comp1 = (const float*)d_in[17];
    const float* root1 = (const float*)d_in[18];
    const float* bias1 = (const float*)d_in[19];
    const float* g1    = (const float*)d_in[20];
    const float* be1   = (const float*)d_in[21];
    const float* postW = (const float*)d_in[22];
    const float* postB = (const float*)d_in[23];

    __half *h0h, *acc0h, *h1h, *acc1h, *h2h;
    int *cnt0, *cnt1, *ovfn0, *ovfn1;
    unsigned int *pay0, *pay1;
    uint2 *ovf0, *ovf1;
    __half *wpreh, *wprel, *w0h, *w0l, *w1h, *w1l, *wposth, *wpostl;
    cudaGetSymbolAddress((void**)&h0h,   g_h0h);
    cudaGetSymbolAddress((void**)&acc0h, g_acc0h);
    cudaGetSymbolAddress((void**)&h1h,   g_h1h);
    cudaGetSymbolAddress((void**)&acc1h, g_acc1h);
    cudaGetSymbolAddress((void**)&h2h,   g_h2h);
    cudaGetSymbolAddress((void**)&cnt0,  g_cnt0);
    cudaGetSymbolAddress((void**)&cnt1,  g_cnt1);
    cudaGetSymbolAddress((void**)&pay0,  g_pay0);
    cudaGetSymbolAddress((void**)&pay1,  g_pay1);
    cudaGetSymbolAddress((void**)&ovfn0, g_ovfn0);
    cudaGetSymbolAddress((void**)&ovfn1, g_ovfn1);
    cudaGetSymbolAddress((void**)&ovf0,  g_ovf0);
    cudaGetSymbolAddress((void**)&ovf1,  g_ovf1);
    cudaGetSymbolAddress((void**)&wpreh, g_WPre_hi);
    cudaGetSymbolAddress((void**)&wprel, g_WPre_lo);
    cudaGetSymbolAddress((void**)&w0h,   g_W0_hi);
    cudaGetSymbolAddress((void**)&w0l,   g_W0_lo);
    cudaGetSymbolAddress((void**)&w1h,   g_W1_hi);
    cudaGetSymbolAddress((void**)&w1l,   g_W1_lo);
    cudaGetSymbolAddress((void**)&wposth, g_WPost_hi);
    cudaGetSymbolAddress((void**)&wpostl, g_WPost_lo);

    cudaFuncSetAttribute((const void*)gemm_k128<MODE_PRE, false>,
                         cudaFuncAttributeMaxDynamicSharedMemorySize, K1_SMEM_NL);
    cudaFuncSetAttribute((const void*)gemm_k128<MODE_POST, true>,
                         cudaFuncAttributeMaxDynamicSharedMemorySize, K1_SMEM);
    cudaFuncSetAttribute(gemm_node, cudaFuncAttributeMaxDynamicSharedMemorySize, SMEM_TOT);

    // 1: fused weight folds + bucketing (counters zero: static init / reset by prior node GEMMs)
    setup_bucket<<<SB_TOTAL, 256>>>(preW, postW, root0, basis0, comp0,
                                    root1, basis1, comp1,
                                    wpreh, wprel, wposth, wpostl,
                                    w0h, w0l, w1h, w1l,
                                    src0, dst0, eid0, src1, dst1, eid1, etall,
                                    cnt0, pay0, ovfn0, ovf0, cnt1, pay1, ovfn1, ovf1);
    // 2: pre-GEMM (single-B)
    gemm_k128<MODE_PRE, false><<<(N0C + 127) / 128, 256, K1_SMEM_NL>>>(
        x, nullptr, wpreh, nullptr, preB, h0h, nullptr, N0C);
    // 3: gather layer 0
    gather_kernel<<<(N1C + 3) / 4, 256>>>(cnt0, pay0, h0h, acc0h, N1C);
    // 4: node0 GEMM (resets cnt0 for next replay)
    gemm_node<<<(N1C + 127) / 128, 256, SMEM_TOT>>>(
        h0h, acc0h, w0h, bias0, g0, be0, h1h, cnt0, N1C);
    // 5: gather layer 1
    gather_kernel<<<(N2C + 3) / 4, 256>>>(cnt1, pay1, h1h, acc1h, N2C);
    // 6: node1 GEMM (resets cnt1)
    gemm_node<<<(N2C + 127) / 128, 256, SMEM_TOT>>>(
        h1h, acc1h, w1h, bias1, g1, be1, h2h, cnt1, N2C);
    // 7: post GEMM (split-B, fp32 out)
    gemm_k128<MODE_POST, true><<<(N2C + 127) / 128, 256, K1_SMEM>>>(
        nullptr, h2h, wposth, wpostl, postB, nullptr, (float*)d_out, N2C);
}